// round 7
// baseline (speedup 1.0000x reference)
#include <cuda_runtime.h>
#include <cuda_bf16.h>

// RKN scan R7: R6 + producer-consumer named barriers (h0/h1 overlap),
// softmax without max-subtraction, diag table in smem (no h0 spills).

#define NB   128
#define NT   128
#define NLOD 128
#define NK   16

__device__ __forceinline__ unsigned int pk(float a, float b) {
    __nv_bfloat162 t = __floats2bfloat162_rn(a, b);
    return reinterpret_cast<unsigned int&>(t);
}
// acc(f32x2) += { lo: p<<16 (exact), hi: raw p (garbage low mantissa) } * {a,a}
__device__ __forceinline__ void pair_fma(unsigned long long& acc,
                                         unsigned int p, unsigned long long a2) {
    asm("{\n\t.reg .b32 lo;\n\t.reg .b64 v;\n\t"
        "shl.b32 lo, %1, 16;\n\t"
        "mov.b64 v, {lo, %1};\n\t"
        "fma.rn.f32x2 %0, v, %2, %0;\n\t}"
        : "+l"(acc) : "r"(p), "l"(a2));
}
__device__ __forceinline__ unsigned long long dup2(float a) {
    unsigned long long r;
    asm("mov.b64 %0, {%1, %1};" : "=l"(r) : "f"(a));
    return r;
}
__device__ __forceinline__ void unpk2(unsigned long long r, float& x, float& y) {
    asm("mov.b64 {%0, %1}, %2;" : "=f"(x), "=f"(y) : "l"(r));
}
__device__ __forceinline__ void bar_sync(int id, int cnt) {
    asm volatile("bar.sync %0, %1;" :: "r"(id), "r"(cnt) : "memory");
}
__device__ __forceinline__ void bar_arrive(int id, int cnt) {
    asm volatile("bar.arrive %0, %1;" :: "r"(id), "r"(cnt) : "memory");
}

#define RED_ROUND(m)                                                          \
  _Pragma("unroll")                                                           \
  for (int k = 0; k < (m); k++) {                                             \
    float a_ = v[k], c_ = v[k + (m)];                                         \
    bool  hi_ = (lane & (m)) != 0;                                            \
    float keep_ = hi_ ? c_ : a_;                                              \
    float send_ = hi_ ? a_ : c_;                                              \
    v[k] = keep_ + __shfl_xor_sync(0xffffffffu, send_, (m));                  \
  }

// state float4 = {mu, ml, cu, cl}; pcs separate
#define BAND_ACC(d, a11, a12, a21, a22)                                       \
  {                                                                           \
    float4 st_ = s_st[i + (d)];                                               \
    float  csj = s_cs[i + (d)];                                               \
    float muj = st_.x, mlj = st_.y, cuj = st_.z, clj = st_.w;                 \
    nmu = fmaf((a11), muj, nmu); nmu = fmaf((a12), mlj, nmu);                 \
    nml = fmaf((a21), muj, nml); nml = fmaf((a22), mlj, nml);                 \
    ncu = fmaf((a11) * (a11), cuj, ncu);                                      \
    ncu = fmaf(2.0f * (a11) * (a12), csj, ncu);                               \
    ncu = fmaf((a12) * (a12), clj, ncu);                                      \
    ncl = fmaf((a21) * (a21), cuj, ncl);                                      \
    ncl = fmaf(2.0f * (a21) * (a22), csj, ncl);                               \
    ncl = fmaf((a22) * (a22), clj, ncl);                                      \
    ncs = fmaf((a21) * (a11), cuj, ncs);                                      \
    ncs = fmaf(fmaf((a22), (a11), (a21) * (a12)), csj, ncs);                  \
    ncs = fmaf((a22) * (a12), clj, ncs);                                      \
  }

// softmax weights, no max subtraction (shift-invariant; logits O(5))
#define SOFTMAX_AW(aw)                                                        \
  {                                                                           \
    const float4* red4_ = reinterpret_cast<const float4*>(red);               \
    float4 rp_ = red4_[lane & 15];                                            \
    float lg_ = bbl + ((rp_.x + rp_.y) + (rp_.z + rp_.w));                    \
    float w_ = __expf(lg_);                                                   \
    float s_ = w_;                                                            \
    _Pragma("unroll")                                                         \
    for (int m_ = 8; m_ >= 1; m_ >>= 1)                                       \
      s_ += __shfl_xor_sync(0xffffffffu, s_, m_);                             \
    (aw) = w_ * (1.0f / s_);                                                  \
  }

__global__ void __launch_bounds__(256, 1)
rkn_kernel(const float* __restrict__ lobs,   // (B,T,LOD)
           const float* __restrict__ ovars,  // (B,T,LOD)
           const float* __restrict__ imean,  // (B,2*LOD)
           const float* __restrict__ icu,
           const float* __restrict__ icl,
           const float* __restrict__ ics,
           const float* __restrict__ tm11,   // (K,LOD,LOD)
           const float* __restrict__ tm12,
           const float* __restrict__ tm21,
           const float* __restrict__ tm22,
           const float* __restrict__ cw,     // (2*LOD, K)
           const float* __restrict__ cb,     // (K,)
           const float* __restrict__ tcu,
           const float* __restrict__ tcl,
           float* __restrict__ out)
{
    __shared__ float4 dg[NK * NLOD];          // fp32 diagonal plane (32 KB)
    __shared__ float4 s_st[136];              // rows -3..132: {mu,ml,cu,cl}
    __shared__ float  s_cs[136];
    __shared__ __align__(16) float red[64];   // red[k*4 + warp]
    __shared__ float4 p4h1[NLOD];             // h1 partial {nmu,nml,ncu,ncl}
    __shared__ float  p1h1[NLOD];             // h1 partial ncs

    const int b    = blockIdx.x;
    const int tid  = threadIdx.x;
    const int lane = tid & 31;
    const int warp = tid >> 5;
    const int i    = tid & 127;   // row
    const int h    = tid >> 7;    // half 0/1

    // ---- prologue (convergent) ----
    for (int r = tid; r < NK * NLOD; r += 256) {
        int k = r >> 7, ii = r & 127;
        long base = ((long)k * NLOD + ii) * NLOD + ii;
        dg[r] = make_float4(__ldg(tm11 + base), __ldg(tm12 + base),
                            __ldg(tm21 + base), __ldg(tm22 + base));
    }
    for (int idx = tid; idx < 136; idx += 256) {
        s_st[idx] = make_float4(0.f, 0.f, 0.f, 0.f);
        s_cs[idx] = 0.f;
    }
    if (h == 1) {
        p4h1[i] = make_float4(0.f, 0.f, 0.f, 0.f);
        p1h1[i] = 0.f;
    }
    const float bbl = __ldg(cb + (lane & 15));

    float* out_pm = out;
    float* out_cu = out + (long)NB * NT * 2 * NLOD;
    float* out_cl = out_cu + (long)NB * NT * NLOD;
    float* out_cs = out_cl + (long)NB * NT * NLOD;

    __syncthreads();

    if (h == 0) {
        // ============ h0: serial head + diagonals {0,1} bf16 + {3} fp32 ============
        float Wu[NK], Wl[NK];
        #pragma unroll
        for (int k = 0; k < NK; k++) {
            Wu[k] = __ldg(cw + i * NK + k);
            Wl[k] = __ldg(cw + (NLOD + i) * NK + k);
        }
        const float tcur = __ldg(tcu + i);
        const float tclr = __ldg(tcl + i);

        uint4 R01[NK];   // bf16 pairs for d0 (j=i-3), d1 (j=i-2)
        {
            const int j0 = i - 3, j1 = i - 2;
            const bool v0 = (j0 >= 0), v1 = (j1 >= 0);
            #pragma unroll
            for (int k = 0; k < NK; k++) {
                long base = ((long)k * NLOD + i) * NLOD;
                float a11 = 0.f, a12 = 0.f, a21 = 0.f, a22 = 0.f;
                float c11 = 0.f, c12 = 0.f, c21 = 0.f, c22 = 0.f;
                if (v0) {
                    a11 = __ldg(tm11 + base + j0); a12 = __ldg(tm12 + base + j0);
                    a21 = __ldg(tm21 + base + j0); a22 = __ldg(tm22 + base + j0);
                }
                if (v1) {
                    c11 = __ldg(tm11 + base + j1); c12 = __ldg(tm12 + base + j1);
                    c21 = __ldg(tm21 + base + j1); c22 = __ldg(tm22 + base + j1);
                }
                R01[k] = make_uint4(pk(a11, a12), pk(a21, a22),
                                    pk(c11, c12), pk(c21, c22));
            }
        }

        // carry partial in registers (tc pre-subtracted; re-added at combine)
        float cmu = imean[(long)b * 2 * NLOD + i];
        float cml = imean[(long)b * 2 * NLOD + NLOD + i];
        float ccu = icu[(long)b * NLOD + i] - tcur;
        float ccl = icl[(long)b * NLOD + i] - tclr;
        float ccs = ics[(long)b * NLOD + i];
        float obs_r = __ldg(lobs  + ((long)b * NT) * NLOD + i);
        float ov_r  = __ldg(ovars + ((long)b * NT) * NLOD + i);

        for (int t = 0; t < NT; t++) {
            // ---- phase 1: combine h1 partial, obs update, logits ----
            float4 pp = p4h1[i];
            float  ps = p1h1[i];
            float pmU = cmu + pp.x;
            float pmL = cml + pp.y;
            float cU  = (ccu + pp.z) + tcur;
            float cL  = (ccl + pp.w) + tclr;
            float cS  = ccs + ps;

            float denom = cU + ov_r;
            float rd    = 1.0f / denom;
            float qu    = cU * rd;
            float ql    = cS * rd;
            float res   = obs_r - pmU;
            float pu    = pmU + qu * res;
            float pl    = pmL + ql * res;
            float cf    = 1.0f - qu;
            float pcu   = cf * cU;
            float pcl   = cL - ql * cS;
            float pcs   = cf * cS;

            if (t + 1 < NT) {
                obs_r = __ldg(lobs  + ((long)b * NT + t + 1) * NLOD + i);
                ov_r  = __ldg(ovars + ((long)b * NT + t + 1) * NLOD + i);
            }

            s_st[3 + i] = make_float4(pu, pl, pcu, pcl);
            s_cs[3 + i] = pcs;

            // logits over 128 rows (value-splitting butterfly)
            float v[NK];
            #pragma unroll
            for (int k = 0; k < NK; k++) v[k] = fmaf(pu, Wu[k], pl * Wl[k]);
            #pragma unroll
            for (int k = 0; k < NK; k++) v[k] += __shfl_xor_sync(0xffffffffu, v[k], 16);
            RED_ROUND(8)
            RED_ROUND(4)
            RED_ROUND(2)
            RED_ROUND(1)
            if (lane < 16) red[lane * 4 + warp] = v[0];
            bar_arrive(1, 256);   // release h1 (red + state published)

            // outputs (off critical path)
            long obase = (long)b * NT + t;
            out_pm[obase * 2 * NLOD + i]        = pu;
            out_pm[obase * 2 * NLOD + NLOD + i] = pl;
            out_cu[obase * NLOD + i] = pcu;
            out_cl[obase * NLOD + i] = pcl;
            out_cs[obase * NLOD + i] = pcs;

            bar_sync(3, 128);     // h0-internal: all h0 warps wrote red

            // ---- phase 2 (concurrent with h1): softmax + d{0,1,3} + matvec ----
            float aw;
            SOFTMAX_AW(aw)

            float D11 = 0.f, D12 = 0.f, D21 = 0.f, D22 = 0.f;
            unsigned long long P0 = 0ull, Q0 = 0ull, P1 = 0ull, Q1 = 0ull;
            #pragma unroll
            for (int k = 0; k < NK; k++) {
                float a = __shfl_sync(0xffffffffu, aw, k);
                unsigned long long a2 = dup2(a);
                uint4 r = R01[k];
                float4 gv = dg[k * NLOD + i];
                pair_fma(P0, r.x, a2);
                pair_fma(Q0, r.y, a2);
                pair_fma(P1, r.z, a2);
                pair_fma(Q1, r.w, a2);
                D11 = fmaf(a, gv.x, D11);
                D12 = fmaf(a, gv.y, D12);
                D21 = fmaf(a, gv.z, D21);
                D22 = fmaf(a, gv.w, D22);
            }
            float nmu = 0.f, nml = 0.f, ncu = 0.f, ncl = 0.f, ncs = 0.f;
            float a11, a12, a21, a22;
            unpk2(P0, a11, a12); unpk2(Q0, a21, a22);
            BAND_ACC(0, a11, a12, a21, a22)
            unpk2(P1, a11, a12); unpk2(Q1, a21, a22);
            BAND_ACC(1, a11, a12, a21, a22)
            BAND_ACC(3, D11 + 1.0f, D12, D21, D22 + 1.0f)

            cmu = nmu; cml = nml; ccu = ncu; ccl = ncl; ccs = ncs;
            bar_sync(2, 256);     // wait for h1's partial (p4h1/p1h1 ready)
        }
    } else {
        // ============ h1: diagonals {2,4,5,6} bf16 ============
        uint4 Ra[NK], Rb[NK];
        {
            const int j2 = i - 1, j4 = i + 1, j5 = i + 2, j6 = i + 3;
            const bool v2 = (j2 >= 0);
            const bool v4 = (j4 < NLOD), v5 = (j5 < NLOD), v6 = (j6 < NLOD);
            #pragma unroll
            for (int k = 0; k < NK; k++) {
                long base = ((long)k * NLOD + i) * NLOD;
                float a11 = 0.f, a12 = 0.f, a21 = 0.f, a22 = 0.f;
                float b11 = 0.f, b12 = 0.f, b21 = 0.f, b22 = 0.f;
                float c11 = 0.f, c12 = 0.f, c21 = 0.f, c22 = 0.f;
                float d11 = 0.f, d12 = 0.f, d21 = 0.f, d22 = 0.f;
                if (v2) {
                    a11 = __ldg(tm11 + base + j2); a12 = __ldg(tm12 + base + j2);
                    a21 = __ldg(tm21 + base + j2); a22 = __ldg(tm22 + base + j2);
                }
                if (v4) {
                    b11 = __ldg(tm11 + base + j4); b12 = __ldg(tm12 + base + j4);
                    b21 = __ldg(tm21 + base + j4); b22 = __ldg(tm22 + base + j4);
                }
                if (v5) {
                    c11 = __ldg(tm11 + base + j5); c12 = __ldg(tm12 + base + j5);
                    c21 = __ldg(tm21 + base + j5); c22 = __ldg(tm22 + base + j5);
                }
                if (v6) {
                    d11 = __ldg(tm11 + base + j6); d12 = __ldg(tm12 + base + j6);
                    d21 = __ldg(tm21 + base + j6); d22 = __ldg(tm22 + base + j6);
                }
                Ra[k] = make_uint4(pk(a11, a12), pk(a21, a22),
                                   pk(b11, b12), pk(b21, b22));
                Rb[k] = make_uint4(pk(c11, c12), pk(c21, c22),
                                   pk(d11, d12), pk(d21, d22));
            }
        }

        for (int t = 0; t < NT; t++) {
            bar_sync(1, 256);     // wait for h0's red + state

            float aw;
            SOFTMAX_AW(aw)

            unsigned long long P2 = 0ull, Q2 = 0ull, P4 = 0ull, Q4 = 0ull;
            unsigned long long P5 = 0ull, Q5 = 0ull, P6 = 0ull, Q6 = 0ull;
            #pragma unroll
            for (int k = 0; k < NK; k++) {
                unsigned long long a2 = dup2(__shfl_sync(0xffffffffu, aw, k));
                uint4 ra = Ra[k], rb = Rb[k];
                pair_fma(P2, ra.x, a2);
                pair_fma(Q2, ra.y, a2);
                pair_fma(P4, ra.z, a2);
                pair_fma(Q4, ra.w, a2);
                pair_fma(P5, rb.x, a2);
                pair_fma(Q5, rb.y, a2);
                pair_fma(P6, rb.z, a2);
                pair_fma(Q6, rb.w, a2);
            }
            float nmu = 0.f, nml = 0.f, ncu = 0.f, ncl = 0.f, ncs = 0.f;
            float a11, a12, a21, a22;
            unpk2(P2, a11, a12); unpk2(Q2, a21, a22);
            BAND_ACC(2, a11, a12, a21, a22)
            unpk2(P4, a11, a12); unpk2(Q4, a21, a22);
            BAND_ACC(4, a11, a12, a21, a22)
            unpk2(P5, a11, a12); unpk2(Q5, a21, a22);
            BAND_ACC(5, a11, a12, a21, a22)
            unpk2(P6, a11, a12); unpk2(Q6, a21, a22);
            BAND_ACC(6, a11, a12, a21, a22)

            p4h1[i] = make_float4(nmu, nml, ncu, ncl);
            p1h1[i] = ncs;
            bar_arrive(2, 256);   // release h0's next phase-1
        }
    }
}

extern "C" void kernel_launch(void* const* d_in, const int* in_sizes, int n_in,
                              void* d_out, int out_size)
{
    (void)in_sizes; (void)n_in; (void)out_size;
    const float* lobs  = (const float*)d_in[0];
    const float* ovars = (const float*)d_in[1];
    const float* imean = (const float*)d_in[2];
    const float* icu   = (const float*)d_in[3];
    const float* icl   = (const float*)d_in[4];
    const float* ics   = (const float*)d_in[5];
    const float* tm11  = (const float*)d_in[6];
    const float* tm12  = (const float*)d_in[7];
    const float* tm21  = (const float*)d_in[8];
    const float* tm22  = (const float*)d_in[9];
    const float* cw    = (const float*)d_in[10];
    const float* cb    = (const float*)d_in[11];
    const float* tcu   = (const float*)d_in[12];
    const float* tcl   = (const float*)d_in[13];
    float* out = (float*)d_out;

    rkn_kernel<<<NB, 256>>>(lobs, ovars, imean, icu, icl, ics,
                            tm11, tm12, tm21, tm22,
                            cw, cb, tcu, tcl, out);
}